// round 14
// baseline (speedup 1.0000x reference)
#include <cuda_runtime.h>
#include <math.h>

#define BB 16
#define LL 21504
#define NN 64
#define CC 80
#define GTS 12           // gt param stride
#define TOPK 13
#define NBLK_L 84        // 21504 / 256
#define CAP 1024         // per-(b,n) candidate buffer

// ---------------- scratch (__device__ globals; no allocation) ----------------
__device__ float d_predg[(size_t)BB * LL * 8];          // x,y,a,b,c,det per pred box
__device__ float d_gtg[BB * NN * GTS];                  // cx,cy,cos,sin,hw,hh,a,b,c,det,pad
__device__ int d_gtlab[BB * NN];
__device__ unsigned long long d_padb[BB];               // pad bitmask per batch
__device__ unsigned int d_maxam[BB * NN];               // float bits, atomicMax (nonneg)
__device__ unsigned int d_maxiou[BB * NN];
__device__ unsigned long long d_pos0[(size_t)BB * LL];  // topk&spatial membership bitmask
__device__ unsigned long long d_pos[(size_t)BB * LL];   // final positive bitmask
__device__ int d_asslab[(size_t)BB * LL];
// candidate buffers
__device__ int d_ccnt[BB * NN];
__device__ unsigned long long d_cand[(size_t)BB * NN * CAP];

// ---------------- bit-exact XLA-shadow ProbIoU ----------------
__device__ __forceinline__ float prob_iou_x(
    float x1, float y1, float a1, float b1, float c1, float det1,
    float x2, float y2, float a2, float b2, float c2, float det2)
{
    float A  = __fadd_rn(a1, a2);
    float Bv = __fadd_rn(b1, b2);
    float Cv = __fadd_rn(c1, c2);
    float denom = __fadd_rn(__fsub_rn(__fmul_rn(A, Bv), __fmul_rn(Cv, Cv)), 1e-7f);
    float dy = __fsub_rn(y1, y2);
    float dx = __fsub_rn(x1, x2);
    float xd = __fsub_rn(x2, x1);
    float t1 = __fdiv_rn(
        __fmul_rn(0.25f, __fadd_rn(__fmul_rn(A, __fmul_rn(dy, dy)),
                                   __fmul_rn(Bv, __fmul_rn(dx, dx)))),
        denom);
    float t2 = __fdiv_rn(
        __fmul_rn(0.5f, __fmul_rn(__fmul_rn(Cv, xd), dy)),
        denom);
    float sq   = __fsqrt_rn(__fmul_rn(det1, det2));
    float den2 = __fadd_rn(__fmul_rn(4.0f, sq), 1e-7f);
    float arg  = __fadd_rn(__fdiv_rn(denom, den2), 1e-7f);
    float t3   = __fmul_rn(0.5f, logf(arg));
    float bd = fminf(fmaxf(__fadd_rn(__fadd_rn(t1, t2), t3), 1e-7f), 100.0f);
    float e  = expf(-bd);
    float s  = __fadd_rn(__fsub_rn(1.0f, e), 1e-7f);
    float hd = __fsqrt_rn(s);
    return fminf(fmaxf(__fsub_rn(1.0f, hd), 0.0f), 1.0f);
}

// align = cls * iou^6 under XLA GPU FTZ semantics (confirmed R4/R6)
__device__ __forceinline__ float align_x(float cls, float iou)
{
    float i2 = __fmul_rn(iou, iou);
    float p6 = __fmul_rn(__fmul_rn(i2, i2), i2);
    if (iou < 0x1p-21f) p6 = 0.0f;
    float al = __fmul_rn(cls, p6);
    if (al < 0x1p-126f) al = 0.0f;
    return al;
}

__device__ __forceinline__ bool spatial_x(float px, float py,
                                          float cx, float cy, float cs, float sn,
                                          float hw, float hh)
{
    float dx = __fsub_rn(px, cx);
    float dy = __fsub_rn(py, cy);
    float sna = -sn;
    float lx = __fsub_rn(__fmul_rn(dx, cs), __fmul_rn(dy, sna));
    float ly = __fadd_rn(__fmul_rn(dx, sna), __fmul_rn(dy, cs));
    return (fabsf(lx) <= hw) && (fabsf(ly) <= hh);
}

__device__ __forceinline__ void gbb_x(float w, float h, float cs, float sn,
                                      float& a, float& b, float& c, float& det)
{
    const float r12 = 1.0f / 12.0f;
    float w2 = __fmul_rn(__fmul_rn(w, w), r12);
    float h2 = __fmul_rn(__fmul_rn(h, h), r12);
    a = __fadd_rn(__fmul_rn(__fmul_rn(w2, cs), cs), __fmul_rn(__fmul_rn(h2, sn), sn));
    b = __fadd_rn(__fmul_rn(__fmul_rn(w2, sn), sn), __fmul_rn(__fmul_rn(h2, cs), cs));
    c = __fmul_rn(__fmul_rn(__fsub_rn(w2, h2), cs), sn);
    det = fmaxf(__fsub_rn(__fmul_rn(a, b), __fmul_rn(c, c)), 0.0f);
}

// ---------------- K_pre: pred params + gt params + zero-init -------
__global__ void k_pre(const float* __restrict__ pb, const float* __restrict__ gtb,
                      const int* __restrict__ gtl, const float* __restrict__ pad)
{
    int g = blockIdx.x * 256 + threadIdx.x;
    if (g >= BB * LL) return;
    d_pos0[g] = 0ull;
    {
        const float* p = pb + (size_t)g * 5;
        float cx = p[0], cy = p[1], w = p[2], h = p[3], ang = p[4];
        float cs = cosf(ang), sn = sinf(ang);
        float a, b, c, det;
        gbb_x(w, h, cs, sn, a, b, c, det);
        float* o = d_predg + (size_t)g * 8;
        ((float4*)o)[0] = make_float4(cx, cy, a, b);
        ((float4*)o)[1] = make_float4(c, det, 0.0f, 0.0f);
    }
    if (g < BB * NN) {
        const float* p = gtb + (size_t)g * 5;
        float cx = p[0], cy = p[1], w = p[2], h = p[3], ang = p[4];
        float cs = cosf(ang), sn = sinf(ang);
        float a, b, c, det;
        gbb_x(w, h, cs, sn, a, b, c, det);
        float* o = d_gtg + g * GTS;
        o[0] = cx; o[1] = cy; o[2] = cs; o[3] = sn;
        o[4] = __fmul_rn(w, 0.5f); o[5] = __fmul_rn(h, 0.5f);
        o[6] = a; o[7] = b; o[8] = c; o[9] = det;
        o[10] = pad[g]; o[11] = 0.0f;
        d_gtlab[g] = gtl[g];
        d_maxam[g] = 0u;
        d_maxiou[g] = 0u;
        d_ccnt[g] = 0;
    }
    if (g < BB) {
        unsigned long long pb64 = 0ull;
        for (int n = 0; n < NN; n++)
            if (pad[g * NN + n] > 0.0f) pb64 |= (1ull << n);
        d_padb[g] = pb64;
    }
}

// ---------------- K_cand: vectorized spatial mask + candidate push ------
__global__ void k_cand(const float* __restrict__ anchors, const float* __restrict__ ps)
{
    int blk = blockIdx.x;
    int b = blk / NBLK_L;
    int l = (blk % NBLK_L) * 256 + threadIdx.x;
    int tid = threadIdx.x;
    size_t gid = (size_t)b * LL + l;

    __shared__ float4 sgA[NN];      // cx, cy, cs, sn
    __shared__ float2 sgB[NN];      // hw, hh
    __shared__ float sg[NN * GTS];  // full params (iou path)
    __shared__ int sL[NN];
    for (int i = tid; i < NN * GTS; i += 256) sg[i] = d_gtg[b * NN * GTS + i];
    if (tid < NN) sL[tid] = d_gtlab[b * NN + tid];
    __syncthreads();
    if (tid < NN) {
        const float* g = sg + tid * GTS;
        sgA[tid] = make_float4(g[0], g[1], g[2], g[3]);
        sgB[tid] = make_float2(g[4], g[5]);
    }
    __syncthreads();

    float px = anchors[2 * l], py = anchors[2 * l + 1];

    unsigned long long spat = 0ull;
#pragma unroll 8
    for (int n = 0; n < NN; n++) {
        float4 A = sgA[n];
        float2 Bv = sgB[n];
        if (spatial_x(px, py, A.x, A.y, A.z, A.w, Bv.x, Bv.y))
            spat |= (1ull << n);
    }

    if (spat && l >= 26) {
        const float* pg = d_predg + gid * 8;
        float4 p0 = ((const float4*)pg)[0];
        float4 p1 = ((const float4*)pg)[1];
        const float* psr = ps + gid * CC;
        unsigned long long m = spat;
        unsigned long long key_lo = (unsigned long long)(0xFFFFFFFFu - (unsigned)l);
        while (m) {
            int n = __ffsll(m) - 1;
            m &= (m - 1);
            const float* g = sg + n * GTS;
            float iou = prob_iou_x(g[0], g[1], g[6], g[7], g[8], g[9],
                                   p0.x, p0.y, p0.z, p0.w, p1.x, p1.y);
            float cls = __ldg(psr + sL[n]);
            float al = align_x(cls, iou);
            if (al > 0.0f) {
                int row = b * NN + n;
                int slot = atomicAdd(&d_ccnt[row], 1);
                if (slot < CAP)
                    d_cand[(size_t)row * CAP + slot] =
                        ((unsigned long long)__float_as_uint(al) << 32) | key_lo;
            }
        }
    }
}

// ---------------- K_sel: exact top-13 per row; spatial folded into scatter ------
__device__ __forceinline__ void topk_insert(unsigned long long* loc, unsigned long long key)
{
    if (key > loc[0]) {
        loc[0] = key;
#pragma unroll
        for (int i = 0; i < TOPK - 1; i++) {
            if (loc[i] > loc[i + 1]) {
                unsigned long long t = loc[i]; loc[i] = loc[i + 1]; loc[i + 1] = t;
            } else break;
        }
    }
}

__global__ void k_sel(const float* __restrict__ anchors, const float* __restrict__ ps)
{
    int row = (blockIdx.x * 256 + threadIdx.x) >> 5;   // global warp = row
    int lane = threadIdx.x & 31;
    int b = row >> 6;
    int n = row & 63;

    unsigned long long loc[TOPK];
#pragma unroll
    for (int i = 0; i < TOPK; i++) loc[i] = 0ull;

    int cnt = min(d_ccnt[row], CAP);
    const unsigned long long* buf = d_cand + (size_t)row * CAP;
    for (int i = lane; i < cnt; i += 32)
        topk_insert(loc, buf[i]);

    bool my_spat = false;
    if (lane < 26) {
        const float* gp = d_gtg + row * GTS;
        float cx = __ldg(gp + 0), cy = __ldg(gp + 1);
        float cs = __ldg(gp + 2), sn = __ldg(gp + 3);
        float hw = __ldg(gp + 4), hh = __ldg(gp + 5);
        int id = lane;
        float px = __ldg(&anchors[2 * id]);
        float py = __ldg(&anchors[2 * id + 1]);
        float ma = 0.0f;
        my_spat = spatial_x(px, py, cx, cy, cs, sn, hw, hh);
        if (my_spat) {
            float ga = __ldg(gp + 6), gb = __ldg(gp + 7), gc = __ldg(gp + 8), gdet = __ldg(gp + 9);
            const float* pg = d_predg + ((size_t)b * LL + id) * 8;
            float iou = prob_iou_x(cx, cy, ga, gb, gc, gdet,
                                   pg[0], pg[1], pg[2], pg[3], pg[4], pg[5]);
            float cls = __ldg(ps + ((size_t)b * LL + id) * CC + __ldg(&d_gtlab[row]));
            ma = align_x(cls, iou);
        }
        unsigned long long key =
            ((unsigned long long)__float_as_uint(ma) << 32) |
            (unsigned long long)(0xFFFFFFFFu - (unsigned)id);
        topk_insert(loc, key);
    }

    int consumed = 0;
    unsigned long long nbit = 1ull << n;
    for (int r = 0; r < TOPK; r++) {
        unsigned long long cand = (consumed < TOPK) ? loc[TOPK - 1 - consumed] : 0ull;
        unsigned long long mx = cand;
#pragma unroll
        for (int s = 16; s > 0; s >>= 1) {
            unsigned long long o = __shfl_xor_sync(0xFFFFFFFFu, mx, s);
            if (o > mx) mx = o;
        }
        if (cand == mx && mx != 0ull) {
            consumed++;
            bool sp_ok = ((mx >> 32) != 0ull) || my_spat;
            if (sp_ok) {
                unsigned l = 0xFFFFFFFFu - (unsigned)(mx & 0xFFFFFFFFull);
                atomicOr(&d_pos0[(size_t)b * LL + l], nbit);
            }
        }
    }
}

// ---------------- K2: per-anchor assignment (bg bbox stores skipped) ----
__global__ void k_assign(const float* __restrict__ anchors, const float* __restrict__ ps,
                         const float* __restrict__ gtb, const int* __restrict__ bgp,
                         float* __restrict__ out)
{
    int blk = blockIdx.x;
    int b = blk / NBLK_L;
    int l = (blk % NBLK_L) * 256 + threadIdx.x;
    int tid = threadIdx.x;
    int lane = tid & 31;
    size_t gid = (size_t)b * LL + l;

    __shared__ unsigned int s_am[NN];
    __shared__ unsigned int s_iou[NN];
    if (tid < NN) { s_am[tid] = 0u; s_iou[tid] = 0u; }
    __syncthreads();

    const float* gtgb = d_gtg + b * NN * GTS;
    const int* labb = d_gtlab + b * NN;
    const float* psr = ps + gid * CC;

    unsigned long long pos = d_pos0[gid] & __ldg(&d_padb[b]);

    float px2 = 0.f, py2 = 0.f, pa = 0.f, pb_ = 0.f, pc = 0.f, pdet = 0.f;
    if (pos) {
        const float* pg = d_predg + gid * 8;
        float4 p0 = ((const float4*)pg)[0];
        float4 p1 = ((const float4*)pg)[1];
        px2 = p0.x; py2 = p0.y; pa = p0.z; pb_ = p0.w; pc = p1.x; pdet = p1.y;
    }

    unsigned cmask = __ballot_sync(0xFFFFFFFFu, __popcll(pos) > 1);
    while (cmask) {
        int src = __ffs(cmask) - 1;
        cmask &= (cmask - 1);
        float bx2 = __shfl_sync(0xFFFFFFFFu, px2, src);
        float by2 = __shfl_sync(0xFFFFFFFFu, py2, src);
        float ba  = __shfl_sync(0xFFFFFFFFu, pa, src);
        float bb  = __shfl_sync(0xFFFFFFFFu, pb_, src);
        float bc  = __shfl_sync(0xFFFFFFFFu, pc, src);
        float bdt = __shfl_sync(0xFFFFFFFFu, pdet, src);
        const float* g0 = gtgb + lane * GTS;
        const float* g1 = gtgb + (lane + 32) * GTS;
        float i0 = prob_iou_x(__ldg(g0 + 0), __ldg(g0 + 1), __ldg(g0 + 6), __ldg(g0 + 7),
                              __ldg(g0 + 8), __ldg(g0 + 9), bx2, by2, ba, bb, bc, bdt);
        float i1 = prob_iou_x(__ldg(g1 + 0), __ldg(g1 + 1), __ldg(g1 + 6), __ldg(g1 + 7),
                              __ldg(g1 + 8), __ldg(g1 + 9), bx2, by2, ba, bb, bc, bdt);
        float mx = fmaxf(i0, i1);
#pragma unroll
        for (int s = 16; s > 0; s >>= 1)
            mx = fmaxf(mx, __shfl_xor_sync(0xFFFFFFFFu, mx, s));
        unsigned long long bits = 0ull;
        if (i0 == mx) bits |= (1ull << lane);
        if (i1 == mx) bits |= (1ull << (lane + 32));
#pragma unroll
        for (int s = 16; s > 0; s >>= 1)
            bits |= __shfl_xor_sync(0xFFFFFFFFu, bits, s);
        if (lane == src) pos = bits;
    }

    unsigned long long m = pos;
    while (m) {
        int n = __ffsll(m) - 1;
        m &= (m - 1);
        const float* g = gtgb + n * GTS;
        float iou = prob_iou_x(__ldg(g + 0), __ldg(g + 1), __ldg(g + 6), __ldg(g + 7),
                               __ldg(g + 8), __ldg(g + 9), px2, py2, pa, pb_, pc, pdet);
        float cls = __ldg(psr + __ldg(&labb[n]));
        float al = align_x(cls, iou);
        atomicMax(&s_am[n], __float_as_uint(al));
        atomicMax(&s_iou[n], __float_as_uint(iou));
    }

    bool fg = (pos != 0ull);
    int an = fg ? (__ffsll(pos) - 1) : 0;
    int bgv = *bgp;
    int lab = fg ? __ldg(&labb[an]) : bgv;

    out[gid] = (float)lab;                                 // assigned_labels
    if (fg) {                                              // bg bboxes pre-zeroed by memset
        const float* gbx = gtb + ((size_t)b * NN + an) * 5;
        float* ob = out + (size_t)BB * LL + gid * 5;
#pragma unroll
        for (int i = 0; i < 5; i++) ob[i] = gbx[i];
    }

    d_pos[gid] = pos;
    d_asslab[gid] = lab;

    __syncthreads();
    if (tid < NN) {
        unsigned int v = s_am[tid];
        if (v) atomicMax(&d_maxam[b * NN + tid], v);
    } else if (tid < 2 * NN) {
        unsigned int v = s_iou[tid - NN];
        if (v) atomicMax(&d_maxiou[b * NN + tid - NN], v);
    }
}

// ---------------- K3: SPARSE scores — one float per fg anchor -------------------
__global__ void k_scores(const float* __restrict__ ps, float* __restrict__ out)
{
    int blk = blockIdx.x;
    int b = blk / NBLK_L;
    int l = (blk % NBLK_L) * 256 + threadIdx.x;
    size_t gid = (size_t)b * LL + l;

    unsigned long long pos = d_pos[gid];
    if (!pos) return;

    const float* pg = d_predg + gid * 8;
    float4 p0 = ((const float4*)pg)[0];
    float4 p1 = ((const float4*)pg)[1];
    const float* psr = ps + gid * CC;
    float norm = 0.0f;
    unsigned long long m = pos;
    while (m) {
        int n = __ffsll(m) - 1;
        m &= (m - 1);
        int row = b * NN + n;
        const float* g = d_gtg + row * GTS;
        float iou = prob_iou_x(g[0], g[1], g[6], g[7], g[8], g[9],
                               p0.x, p0.y, p0.z, p0.w, p1.x, p1.y);
        float cls = __ldg(psr + d_gtlab[row]);
        float al = align_x(cls, iou);
        float ma = __uint_as_float(d_maxam[row]);
        float mi = __uint_as_float(d_maxiou[row]);
        float v = __fmul_rn(__fdiv_rn(al, __fadd_rn(ma, 1e-9f)), mi);
        norm = fmaxf(norm, v);
    }
    int lab = d_asslab[gid];
    out[(size_t)BB * LL * 6 + gid * CC + lab] = norm;      // rest pre-zeroed by memset
}

// ---------------- launch: fork memset onto a 2nd stream, overlapped -------------
extern "C" void kernel_launch(void* const* d_in, const int* in_sizes, int n_in,
                              void* d_out, int out_size)
{
    const float* pred_scores = (const float*)d_in[0];   // (B,L,C)
    const float* pred_bboxes = (const float*)d_in[1];   // (B,L,5)
    const float* anchors     = (const float*)d_in[2];   // (1,L,2)
    const int*   gt_labels   = (const int*)d_in[3];     // (B,N,1)
    const float* gt_bboxes   = (const float*)d_in[4];   // (B,N,5)
    const float* pad_mask    = (const float*)d_in[5];   // (B,N,1)
    const int*   bg_index    = (const int*)d_in[6];     // scalar
    float* out = (float*)d_out;

    // second stream + events (created per call; NOT destroyed — destroying during an
    // active capture would invalidate the graph; ~2 calls total, no device memory)
    cudaStream_t s2;
    cudaEvent_t e1, e2;
    cudaStreamCreateWithFlags(&s2, cudaStreamNonBlocking);
    cudaEventCreateWithFlags(&e1, cudaEventDisableTiming);
    cudaEventCreateWithFlags(&e2, cudaEventDisableTiming);

    // fork: zero the whole output on s2 while the compute chain runs
    cudaEventRecord(e1, 0);
    cudaStreamWaitEvent(s2, e1, 0);
    cudaMemsetAsync(out, 0, (size_t)out_size * sizeof(float), s2);
    cudaEventRecord(e2, s2);

    k_pre<<<(BB * LL + 255) / 256, 256>>>(pred_bboxes, gt_bboxes, gt_labels, pad_mask);
    k_cand<<<BB * NBLK_L, 256>>>(anchors, pred_scores);
    k_sel<<<(BB * NN) / 8, 256>>>(anchors, pred_scores);

    // join: k_assign writes into the zeroed buffer
    cudaStreamWaitEvent(0, e2, 0);
    k_assign<<<BB * NBLK_L, 256>>>(anchors, pred_scores, gt_bboxes, bg_index, out);
    k_scores<<<BB * NBLK_L, 256>>>(pred_scores, out);
}

// round 15
// speedup vs baseline: 1.0952x; 1.0952x over previous
#include <cuda_runtime.h>
#include <math.h>

#define BB 16
#define LL 21504
#define NN 64
#define CC 80
#define GTS 12           // gt param stride
#define TOPK 13
#define NBLK_L 84        // 21504 / 256
#define CAP 1024         // per-(b,n) candidate buffer

// ---------------- scratch (__device__ globals; no allocation) ----------------
__device__ float d_predg[(size_t)BB * LL * 8];          // x,y,a,b,c,det per pred box
__device__ float d_gtg[BB * NN * GTS];                  // cx,cy,cos,sin,hw,hh,a,b,c,det,pad
__device__ int d_gtlab[BB * NN];
__device__ unsigned long long d_padb[BB];               // pad bitmask per batch
__device__ unsigned int d_maxam[BB * NN];               // float bits, atomicMax (nonneg)
__device__ unsigned int d_maxiou[BB * NN];
__device__ unsigned long long d_pos0[(size_t)BB * LL];  // topk&spatial membership bitmask
__device__ ulonglong2 d_poslab[(size_t)BB * LL];        // {final pos bitmask, label}
// candidate buffers
__device__ int d_ccnt[BB * NN];
__device__ unsigned long long d_cand[(size_t)BB * NN * CAP];

// ---------------- bit-exact XLA-shadow ProbIoU ----------------
__device__ __forceinline__ float prob_iou_x(
    float x1, float y1, float a1, float b1, float c1, float det1,
    float x2, float y2, float a2, float b2, float c2, float det2)
{
    float A  = __fadd_rn(a1, a2);
    float Bv = __fadd_rn(b1, b2);
    float Cv = __fadd_rn(c1, c2);
    float denom = __fadd_rn(__fsub_rn(__fmul_rn(A, Bv), __fmul_rn(Cv, Cv)), 1e-7f);
    float dy = __fsub_rn(y1, y2);
    float dx = __fsub_rn(x1, x2);
    float xd = __fsub_rn(x2, x1);
    float t1 = __fdiv_rn(
        __fmul_rn(0.25f, __fadd_rn(__fmul_rn(A, __fmul_rn(dy, dy)),
                                   __fmul_rn(Bv, __fmul_rn(dx, dx)))),
        denom);
    float t2 = __fdiv_rn(
        __fmul_rn(0.5f, __fmul_rn(__fmul_rn(Cv, xd), dy)),
        denom);
    float sq   = __fsqrt_rn(__fmul_rn(det1, det2));
    float den2 = __fadd_rn(__fmul_rn(4.0f, sq), 1e-7f);
    float arg  = __fadd_rn(__fdiv_rn(denom, den2), 1e-7f);
    float t3   = __fmul_rn(0.5f, logf(arg));
    float bd = fminf(fmaxf(__fadd_rn(__fadd_rn(t1, t2), t3), 1e-7f), 100.0f);
    float e  = expf(-bd);
    float s  = __fadd_rn(__fsub_rn(1.0f, e), 1e-7f);
    float hd = __fsqrt_rn(s);
    return fminf(fmaxf(__fsub_rn(1.0f, hd), 0.0f), 1.0f);
}

// align = cls * iou^6 under XLA GPU FTZ semantics (confirmed R4/R6)
__device__ __forceinline__ float align_x(float cls, float iou)
{
    float i2 = __fmul_rn(iou, iou);
    float p6 = __fmul_rn(__fmul_rn(i2, i2), i2);
    if (iou < 0x1p-21f) p6 = 0.0f;
    float al = __fmul_rn(cls, p6);
    if (al < 0x1p-126f) al = 0.0f;
    return al;
}

__device__ __forceinline__ bool spatial_x(float px, float py,
                                          float cx, float cy, float cs, float sn,
                                          float hw, float hh)
{
    float dx = __fsub_rn(px, cx);
    float dy = __fsub_rn(py, cy);
    float sna = -sn;
    float lx = __fsub_rn(__fmul_rn(dx, cs), __fmul_rn(dy, sna));
    float ly = __fadd_rn(__fmul_rn(dx, sna), __fmul_rn(dy, cs));
    return (fabsf(lx) <= hw) && (fabsf(ly) <= hh);
}

__device__ __forceinline__ void gbb_x(float w, float h, float cs, float sn,
                                      float& a, float& b, float& c, float& det)
{
    const float r12 = 1.0f / 12.0f;
    float w2 = __fmul_rn(__fmul_rn(w, w), r12);
    float h2 = __fmul_rn(__fmul_rn(h, h), r12);
    a = __fadd_rn(__fmul_rn(__fmul_rn(w2, cs), cs), __fmul_rn(__fmul_rn(h2, sn), sn));
    b = __fadd_rn(__fmul_rn(__fmul_rn(w2, sn), sn), __fmul_rn(__fmul_rn(h2, cs), cs));
    c = __fmul_rn(__fmul_rn(__fsub_rn(w2, h2), cs), sn);
    det = fmaxf(__fsub_rn(__fmul_rn(a, b), __fmul_rn(c, c)), 0.0f);
}

// ---------------- K_pre: pred params + gt params + zero-init -------
__global__ void k_pre(const float* __restrict__ pb, const float* __restrict__ gtb,
                      const int* __restrict__ gtl, const float* __restrict__ pad)
{
    int g = blockIdx.x * 256 + threadIdx.x;
    if (g >= BB * LL) return;
    d_pos0[g] = 0ull;
    {
        const float* p = pb + (size_t)g * 5;
        float cx = p[0], cy = p[1], w = p[2], h = p[3], ang = p[4];
        float cs = cosf(ang), sn = sinf(ang);
        float a, b, c, det;
        gbb_x(w, h, cs, sn, a, b, c, det);
        float* o = d_predg + (size_t)g * 8;
        ((float4*)o)[0] = make_float4(cx, cy, a, b);
        ((float4*)o)[1] = make_float4(c, det, 0.0f, 0.0f);
    }
    if (g < BB * NN) {
        const float* p = gtb + (size_t)g * 5;
        float cx = p[0], cy = p[1], w = p[2], h = p[3], ang = p[4];
        float cs = cosf(ang), sn = sinf(ang);
        float a, b, c, det;
        gbb_x(w, h, cs, sn, a, b, c, det);
        float* o = d_gtg + g * GTS;
        o[0] = cx; o[1] = cy; o[2] = cs; o[3] = sn;
        o[4] = __fmul_rn(w, 0.5f); o[5] = __fmul_rn(h, 0.5f);
        o[6] = a; o[7] = b; o[8] = c; o[9] = det;
        o[10] = pad[g]; o[11] = 0.0f;
        d_gtlab[g] = gtl[g];
        d_maxam[g] = 0u;
        d_maxiou[g] = 0u;
        d_ccnt[g] = 0;
    }
    if (g < BB) {
        unsigned long long pb64 = 0ull;
        for (int n = 0; n < NN; n++)
            if (pad[g * NN + n] > 0.0f) pb64 |= (1ull << n);
        d_padb[g] = pb64;
    }
}

// ---------------- K_cand: vectorized spatial mask + candidate push ------
__global__ void k_cand(const float* __restrict__ anchors, const float* __restrict__ ps)
{
    int blk = blockIdx.x;
    int b = blk / NBLK_L;
    int l = (blk % NBLK_L) * 256 + threadIdx.x;
    int tid = threadIdx.x;
    size_t gid = (size_t)b * LL + l;

    __shared__ float4 sgA[NN];      // cx, cy, cs, sn
    __shared__ float2 sgB[NN];      // hw, hh
    __shared__ float sg[NN * GTS];  // full params (iou path)
    __shared__ int sL[NN];
    for (int i = tid; i < NN * GTS; i += 256) sg[i] = d_gtg[b * NN * GTS + i];
    if (tid < NN) sL[tid] = d_gtlab[b * NN + tid];
    __syncthreads();
    if (tid < NN) {
        const float* g = sg + tid * GTS;
        sgA[tid] = make_float4(g[0], g[1], g[2], g[3]);
        sgB[tid] = make_float2(g[4], g[5]);
    }
    __syncthreads();

    float px = anchors[2 * l], py = anchors[2 * l + 1];

    unsigned long long spat = 0ull;
#pragma unroll 8
    for (int n = 0; n < NN; n++) {
        float4 A = sgA[n];
        float2 Bv = sgB[n];
        if (spatial_x(px, py, A.x, A.y, A.z, A.w, Bv.x, Bv.y))
            spat |= (1ull << n);
    }

    if (spat && l >= 26) {
        const float* pg = d_predg + gid * 8;
        float4 p0 = ((const float4*)pg)[0];
        float4 p1 = ((const float4*)pg)[1];
        const float* psr = ps + gid * CC;
        unsigned long long m = spat;
        unsigned long long key_lo = (unsigned long long)(0xFFFFFFFFu - (unsigned)l);
        while (m) {
            int n = __ffsll(m) - 1;
            m &= (m - 1);
            const float* g = sg + n * GTS;
            float iou = prob_iou_x(g[0], g[1], g[6], g[7], g[8], g[9],
                                   p0.x, p0.y, p0.z, p0.w, p1.x, p1.y);
            float cls = __ldg(psr + sL[n]);
            float al = align_x(cls, iou);
            if (al > 0.0f) {
                int row = b * NN + n;
                int slot = atomicAdd(&d_ccnt[row], 1);
                if (slot < CAP)
                    d_cand[(size_t)row * CAP + slot] =
                        ((unsigned long long)__float_as_uint(al) << 32) | key_lo;
            }
        }
    }
}

// ---------------- K_sel: exact top-13 per row; spatial folded into scatter ------
__device__ __forceinline__ void topk_insert(unsigned long long* loc, unsigned long long key)
{
    if (key > loc[0]) {
        loc[0] = key;
#pragma unroll
        for (int i = 0; i < TOPK - 1; i++) {
            if (loc[i] > loc[i + 1]) {
                unsigned long long t = loc[i]; loc[i] = loc[i + 1]; loc[i + 1] = t;
            } else break;
        }
    }
}

__global__ void k_sel(const float* __restrict__ anchors, const float* __restrict__ ps)
{
    int row = (blockIdx.x * 256 + threadIdx.x) >> 5;   // global warp = row
    int lane = threadIdx.x & 31;
    int b = row >> 6;
    int n = row & 63;

    unsigned long long loc[TOPK];
#pragma unroll
    for (int i = 0; i < TOPK; i++) loc[i] = 0ull;

    int cnt = min(d_ccnt[row], CAP);
    const unsigned long long* buf = d_cand + (size_t)row * CAP;
    for (int i = lane; i < cnt; i += 32)
        topk_insert(loc, buf[i]);

    bool my_spat = false;
    if (lane < 26) {
        const float* gp = d_gtg + row * GTS;
        float cx = __ldg(gp + 0), cy = __ldg(gp + 1);
        float cs = __ldg(gp + 2), sn = __ldg(gp + 3);
        float hw = __ldg(gp + 4), hh = __ldg(gp + 5);
        int id = lane;
        float px = __ldg(&anchors[2 * id]);
        float py = __ldg(&anchors[2 * id + 1]);
        float ma = 0.0f;
        my_spat = spatial_x(px, py, cx, cy, cs, sn, hw, hh);
        if (my_spat) {
            float ga = __ldg(gp + 6), gb = __ldg(gp + 7), gc = __ldg(gp + 8), gdet = __ldg(gp + 9);
            const float* pg = d_predg + ((size_t)b * LL + id) * 8;
            float iou = prob_iou_x(cx, cy, ga, gb, gc, gdet,
                                   pg[0], pg[1], pg[2], pg[3], pg[4], pg[5]);
            float cls = __ldg(ps + ((size_t)b * LL + id) * CC + __ldg(&d_gtlab[row]));
            ma = align_x(cls, iou);
        }
        unsigned long long key =
            ((unsigned long long)__float_as_uint(ma) << 32) |
            (unsigned long long)(0xFFFFFFFFu - (unsigned)id);
        topk_insert(loc, key);
    }

    int consumed = 0;
    unsigned long long nbit = 1ull << n;
    for (int r = 0; r < TOPK; r++) {
        unsigned long long cand = (consumed < TOPK) ? loc[TOPK - 1 - consumed] : 0ull;
        unsigned long long mx = cand;
#pragma unroll
        for (int s = 16; s > 0; s >>= 1) {
            unsigned long long o = __shfl_xor_sync(0xFFFFFFFFu, mx, s);
            if (o > mx) mx = o;
        }
        if (cand == mx && mx != 0ull) {
            consumed++;
            bool sp_ok = ((mx >> 32) != 0ull) || my_spat;
            if (sp_ok) {
                unsigned l = 0xFFFFFFFFu - (unsigned)(mx & 0xFFFFFFFFull);
                atomicOr(&d_pos0[(size_t)b * LL + l], nbit);
            }
        }
    }
}

// ---------------- K2: assignment + dense zero-fill of scores region -------------
__global__ void k_assign(const float* __restrict__ ps,
                         const float* __restrict__ gtb, const int* __restrict__ bgp,
                         float* __restrict__ out)
{
    int blk = blockIdx.x;
    int b = blk / NBLK_L;
    int l0 = (blk % NBLK_L) * 256;
    int tid = threadIdx.x;
    int l = l0 + tid;
    int lane = tid & 31;
    size_t gid = (size_t)b * LL + l;

    // dense zero-fill of this block's scores rows — fire-and-forget stores that
    // use the idle DRAM bandwidth while the latency chain below proceeds
    {
        float4 z4 = make_float4(0.f, 0.f, 0.f, 0.f);
        float4* sc4 = (float4*)(out + (size_t)BB * LL * 6 + ((size_t)b * LL + l0) * CC);
#pragma unroll
        for (int it = 0; it < 20; it++)
            sc4[tid + it * 256] = z4;
    }

    __shared__ unsigned int s_am[NN];
    __shared__ unsigned int s_iou[NN];
    if (tid < NN) { s_am[tid] = 0u; s_iou[tid] = 0u; }
    __syncthreads();

    const float* gtgb = d_gtg + b * NN * GTS;
    const int* labb = d_gtlab + b * NN;
    const float* psr = ps + gid * CC;

    unsigned long long pos = d_pos0[gid] & __ldg(&d_padb[b]);

    // unconditional pred-param load (breaks the dependent branch)
    const float* pg = d_predg + gid * 8;
    float4 p0 = ((const float4*)pg)[0];
    float4 p1 = ((const float4*)pg)[1];
    float px2 = p0.x, py2 = p0.y, pa = p0.z, pb_ = p0.w, pc = p1.x, pdet = p1.y;

    unsigned cmask = __ballot_sync(0xFFFFFFFFu, __popcll(pos) > 1);
    while (cmask) {
        int src = __ffs(cmask) - 1;
        cmask &= (cmask - 1);
        float bx2 = __shfl_sync(0xFFFFFFFFu, px2, src);
        float by2 = __shfl_sync(0xFFFFFFFFu, py2, src);
        float ba  = __shfl_sync(0xFFFFFFFFu, pa, src);
        float bb  = __shfl_sync(0xFFFFFFFFu, pb_, src);
        float bc  = __shfl_sync(0xFFFFFFFFu, pc, src);
        float bdt = __shfl_sync(0xFFFFFFFFu, pdet, src);
        const float* g0 = gtgb + lane * GTS;
        const float* g1 = gtgb + (lane + 32) * GTS;
        float i0 = prob_iou_x(__ldg(g0 + 0), __ldg(g0 + 1), __ldg(g0 + 6), __ldg(g0 + 7),
                              __ldg(g0 + 8), __ldg(g0 + 9), bx2, by2, ba, bb, bc, bdt);
        float i1 = prob_iou_x(__ldg(g1 + 0), __ldg(g1 + 1), __ldg(g1 + 6), __ldg(g1 + 7),
                              __ldg(g1 + 8), __ldg(g1 + 9), bx2, by2, ba, bb, bc, bdt);
        float mx = fmaxf(i0, i1);
#pragma unroll
        for (int s = 16; s > 0; s >>= 1)
            mx = fmaxf(mx, __shfl_xor_sync(0xFFFFFFFFu, mx, s));
        unsigned long long bits = 0ull;
        if (i0 == mx) bits |= (1ull << lane);
        if (i1 == mx) bits |= (1ull << (lane + 32));
#pragma unroll
        for (int s = 16; s > 0; s >>= 1)
            bits |= __shfl_xor_sync(0xFFFFFFFFu, bits, s);
        if (lane == src) pos = bits;
    }

    unsigned long long m = pos;
    while (m) {
        int n = __ffsll(m) - 1;
        m &= (m - 1);
        const float* g = gtgb + n * GTS;
        float iou = prob_iou_x(__ldg(g + 0), __ldg(g + 1), __ldg(g + 6), __ldg(g + 7),
                               __ldg(g + 8), __ldg(g + 9), px2, py2, pa, pb_, pc, pdet);
        float cls = __ldg(psr + __ldg(&labb[n]));
        float al = align_x(cls, iou);
        atomicMax(&s_am[n], __float_as_uint(al));
        atomicMax(&s_iou[n], __float_as_uint(iou));
    }

    bool fg = (pos != 0ull);
    int an = fg ? (__ffsll(pos) - 1) : 0;
    int bgv = *bgp;
    int lab = fg ? __ldg(&labb[an]) : bgv;

    out[gid] = (float)lab;                                 // assigned_labels
    const float* gbx = gtb + ((size_t)b * NN + an) * 5;
    float* ob = out + (size_t)BB * LL + gid * 5;           // assigned_bboxes
#pragma unroll
    for (int i = 0; i < 5; i++) ob[i] = fg ? gbx[i] : 0.0f;

    d_poslab[gid] = make_ulonglong2(pos, (unsigned long long)lab);

    __syncthreads();
    if (tid < NN) {
        unsigned int v = s_am[tid];
        if (v) atomicMax(&d_maxam[b * NN + tid], v);
    } else if (tid < 2 * NN) {
        unsigned int v = s_iou[tid - NN];
        if (v) atomicMax(&d_maxiou[b * NN + tid - NN], v);
    }
}

// ---------------- K3: SPARSE norm write (scores pre-zeroed in k_assign) ---------
__global__ void k_scores(const float* __restrict__ ps, float* __restrict__ out)
{
    int blk = blockIdx.x;
    int b = blk / NBLK_L;
    int l = (blk % NBLK_L) * 256 + threadIdx.x;
    size_t gid = (size_t)b * LL + l;

    ulonglong2 pl = d_poslab[gid];
    unsigned long long pos = pl.x;
    if (!pos) return;

    const float* pg = d_predg + gid * 8;
    float4 p0 = ((const float4*)pg)[0];
    float4 p1 = ((const float4*)pg)[1];
    const float* psr = ps + gid * CC;
    float norm = 0.0f;
    unsigned long long m = pos;
    while (m) {
        int n = __ffsll(m) - 1;
        m &= (m - 1);
        int row = b * NN + n;
        const float* g = d_gtg + row * GTS;
        float iou = prob_iou_x(g[0], g[1], g[6], g[7], g[8], g[9],
                               p0.x, p0.y, p0.z, p0.w, p1.x, p1.y);
        float cls = __ldg(psr + d_gtlab[row]);
        float al = align_x(cls, iou);
        float ma = __uint_as_float(d_maxam[row]);
        float mi = __uint_as_float(d_maxiou[row]);
        float v = __fmul_rn(__fdiv_rn(al, __fadd_rn(ma, 1e-9f)), mi);
        norm = fmaxf(norm, v);
    }
    int lab = (int)pl.y;
    out[(size_t)BB * LL * 6 + gid * CC + lab] = norm;
}

// ---------------- launch ----------------
extern "C" void kernel_launch(void* const* d_in, const int* in_sizes, int n_in,
                              void* d_out, int out_size)
{
    const float* pred_scores = (const float*)d_in[0];   // (B,L,C)
    const float* pred_bboxes = (const float*)d_in[1];   // (B,L,5)
    const float* anchors     = (const float*)d_in[2];   // (1,L,2)
    const int*   gt_labels   = (const int*)d_in[3];     // (B,N,1)
    const float* gt_bboxes   = (const float*)d_in[4];   // (B,N,5)
    const float* pad_mask    = (const float*)d_in[5];   // (B,N,1)
    const int*   bg_index    = (const int*)d_in[6];     // scalar
    float* out = (float*)d_out;

    k_pre<<<(BB * LL + 255) / 256, 256>>>(pred_bboxes, gt_bboxes, gt_labels, pad_mask);
    k_cand<<<BB * NBLK_L, 256>>>(anchors, pred_scores);
    k_sel<<<(BB * NN) / 8, 256>>>(anchors, pred_scores);
    k_assign<<<BB * NBLK_L, 256>>>(pred_scores, gt_bboxes, bg_index, out);
    k_scores<<<BB * NBLK_L, 256>>>(pred_scores, out);
}

// round 16
// speedup vs baseline: 1.1514x; 1.0513x over previous
#include <cuda_runtime.h>
#include <math.h>

#define BB 16
#define LL 21504
#define NN 64
#define CC 80
#define GTS 12           // gt param stride
#define TOPK 13
#define NBLK_L 84        // 21504 / 256
#define CAP 1024         // per-(b,n) candidate buffer

// ---------------- scratch (__device__ globals; no allocation) ----------------
__device__ float d_predg[(size_t)BB * LL * 8];          // x,y,a,b,c,det (spat anchors only)
__device__ float d_gtg[BB * NN * GTS];                  // cx,cy,cos,sin,hw,hh,a,b,c,det,pad
__device__ unsigned long long d_padb[BB];               // pad bitmask per batch
__device__ unsigned int d_maxam[BB * NN];               // float bits, atomicMax (nonneg)
__device__ unsigned int d_maxiou[BB * NN];
__device__ unsigned long long d_pos0[(size_t)BB * LL];  // topk&spatial membership bitmask
__device__ ulonglong2 d_poslab[(size_t)BB * LL];        // {final pos bitmask, label}
// candidate buffers (d_ccnt recycled: zeroed by k_sel each call -> replay-safe)
__device__ int d_ccnt[BB * NN];
__device__ unsigned long long d_cand[(size_t)BB * NN * CAP];

// ---------------- bit-exact XLA-shadow ProbIoU ----------------
__device__ __forceinline__ float prob_iou_x(
    float x1, float y1, float a1, float b1, float c1, float det1,
    float x2, float y2, float a2, float b2, float c2, float det2)
{
    float A  = __fadd_rn(a1, a2);
    float Bv = __fadd_rn(b1, b2);
    float Cv = __fadd_rn(c1, c2);
    float denom = __fadd_rn(__fsub_rn(__fmul_rn(A, Bv), __fmul_rn(Cv, Cv)), 1e-7f);
    float dy = __fsub_rn(y1, y2);
    float dx = __fsub_rn(x1, x2);
    float xd = __fsub_rn(x2, x1);
    float t1 = __fdiv_rn(
        __fmul_rn(0.25f, __fadd_rn(__fmul_rn(A, __fmul_rn(dy, dy)),
                                   __fmul_rn(Bv, __fmul_rn(dx, dx)))),
        denom);
    float t2 = __fdiv_rn(
        __fmul_rn(0.5f, __fmul_rn(__fmul_rn(Cv, xd), dy)),
        denom);
    float sq   = __fsqrt_rn(__fmul_rn(det1, det2));
    float den2 = __fadd_rn(__fmul_rn(4.0f, sq), 1e-7f);
    float arg  = __fadd_rn(__fdiv_rn(denom, den2), 1e-7f);
    float t3   = __fmul_rn(0.5f, logf(arg));
    float bd = fminf(fmaxf(__fadd_rn(__fadd_rn(t1, t2), t3), 1e-7f), 100.0f);
    float e  = expf(-bd);
    float s  = __fadd_rn(__fsub_rn(1.0f, e), 1e-7f);
    float hd = __fsqrt_rn(s);
    return fminf(fmaxf(__fsub_rn(1.0f, hd), 0.0f), 1.0f);
}

// align = cls * iou^6 under XLA GPU FTZ semantics (confirmed R4/R6)
__device__ __forceinline__ float align_x(float cls, float iou)
{
    float i2 = __fmul_rn(iou, iou);
    float p6 = __fmul_rn(__fmul_rn(i2, i2), i2);
    if (iou < 0x1p-21f) p6 = 0.0f;
    float al = __fmul_rn(cls, p6);
    if (al < 0x1p-126f) al = 0.0f;
    return al;
}

__device__ __forceinline__ bool spatial_x(float px, float py,
                                          float cx, float cy, float cs, float sn,
                                          float hw, float hh)
{
    float dx = __fsub_rn(px, cx);
    float dy = __fsub_rn(py, cy);
    float sna = -sn;
    float lx = __fsub_rn(__fmul_rn(dx, cs), __fmul_rn(dy, sna));
    float ly = __fadd_rn(__fmul_rn(dx, sna), __fmul_rn(dy, cs));
    return (fabsf(lx) <= hw) && (fabsf(ly) <= hh);
}

__device__ __forceinline__ void gbb_x(float w, float h, float cs, float sn,
                                      float& a, float& b, float& c, float& det)
{
    const float r12 = 1.0f / 12.0f;
    float w2 = __fmul_rn(__fmul_rn(w, w), r12);
    float h2 = __fmul_rn(__fmul_rn(h, h), r12);
    a = __fadd_rn(__fmul_rn(__fmul_rn(w2, cs), cs), __fmul_rn(__fmul_rn(h2, sn), sn));
    b = __fadd_rn(__fmul_rn(__fmul_rn(w2, sn), sn), __fmul_rn(__fmul_rn(h2, cs), cs));
    c = __fmul_rn(__fmul_rn(__fsub_rn(w2, h2), cs), sn);
    det = fmaxf(__fsub_rn(__fmul_rn(a, b), __fmul_rn(c, c)), 0.0f);
}

// ---------------- K_cand: self-contained — GT params in smem, lazy pred params,
//                  spatial mask + candidate push; leader block publishes globals ----
__global__ void k_cand(const float* __restrict__ anchors, const float* __restrict__ ps,
                       const float* __restrict__ pb, const float* __restrict__ gtb,
                       const int* __restrict__ gtl, const float* __restrict__ pad)
{
    int blk = blockIdx.x;
    int b = blk / NBLK_L;
    int l = (blk % NBLK_L) * 256 + threadIdx.x;
    int tid = threadIdx.x;
    size_t gid = (size_t)b * LL + l;

    __shared__ float4 sgA[NN];      // cx, cy, cs, sn
    __shared__ float2 sgB[NN];      // hw, hh
    __shared__ float sg[NN * GTS];  // full params (iou path)
    __shared__ int sL[NN];
    __shared__ unsigned s_padw[2];

    if (tid < NN) {
        const float* p = gtb + (size_t)(b * NN + tid) * 5;
        float cx = p[0], cy = p[1], w = p[2], h = p[3], ang = p[4];
        float cs = cosf(ang), sn = sinf(ang);
        float a, bb_, c, det;
        gbb_x(w, h, cs, sn, a, bb_, c, det);
        float* o = sg + tid * GTS;
        o[0] = cx; o[1] = cy; o[2] = cs; o[3] = sn;
        o[4] = __fmul_rn(w, 0.5f); o[5] = __fmul_rn(h, 0.5f);
        o[6] = a; o[7] = bb_; o[8] = c; o[9] = det;
        o[10] = 0.0f; o[11] = 0.0f;
        sgA[tid] = make_float4(cx, cy, cs, sn);
        sgB[tid] = make_float2(o[4], o[5]);
        sL[tid] = gtl[b * NN + tid];
        bool pd = pad[b * NN + tid] > 0.0f;
        unsigned bal = __ballot_sync(0xFFFFFFFFu, pd);
        if ((tid & 31) == 0) s_padw[tid >> 5] = bal;
    }
    d_pos0[gid] = 0ull;
    __syncthreads();

    // per-batch leader block publishes GT params + pad bitmask for later kernels
    if ((blk % NBLK_L) == 0) {
        for (int i = tid; i < NN * GTS; i += 256) d_gtg[b * NN * GTS + i] = sg[i];
        if (tid == 0)
            d_padb[b] = ((unsigned long long)s_padw[1] << 32) | (unsigned long long)s_padw[0];
    }

    float px = anchors[2 * l], py = anchors[2 * l + 1];

    unsigned long long spat = 0ull;
#pragma unroll 8
    for (int n = 0; n < NN; n++) {
        float4 A = sgA[n];
        float2 Bv = sgB[n];
        if (spatial_x(px, py, A.x, A.y, A.z, A.w, Bv.x, Bv.y))
            spat |= (1ull << n);
    }

    if (spat) {
        // lazy pred gaussian params (only ~30% of anchors reach here)
        const float* p = pb + gid * 5;
        float cx = p[0], cy = p[1], w = p[2], h = p[3], ang = p[4];
        float cs = cosf(ang), sn = sinf(ang);
        float a, bb_, c, det;
        gbb_x(w, h, cs, sn, a, bb_, c, det);
        float4 p0 = make_float4(cx, cy, a, bb_);
        float4 p1 = make_float4(c, det, 0.0f, 0.0f);
        float* o = d_predg + gid * 8;
        ((float4*)o)[0] = p0;
        ((float4*)o)[1] = p1;

        if (l >= 26) {
            const float* psr = ps + gid * CC;
            unsigned long long m = spat;
            unsigned long long key_lo = (unsigned long long)(0xFFFFFFFFu - (unsigned)l);
            while (m) {
                int n = __ffsll(m) - 1;
                m &= (m - 1);
                const float* g = sg + n * GTS;
                float iou = prob_iou_x(g[0], g[1], g[6], g[7], g[8], g[9],
                                       p0.x, p0.y, p0.z, p0.w, p1.x, p1.y);
                float cls = __ldg(psr + sL[n]);
                float al = align_x(cls, iou);
                if (al > 0.0f) {
                    int row = b * NN + n;
                    int slot = atomicAdd(&d_ccnt[row], 1);
                    if (slot < CAP)
                        d_cand[(size_t)row * CAP + slot] =
                            ((unsigned long long)__float_as_uint(al) << 32) | key_lo;
                }
            }
        }
    }
}

// ---------------- K_sel: exact top-13 per row; recycles counters for replay -----
__device__ __forceinline__ void topk_insert(unsigned long long* loc, unsigned long long key)
{
    if (key > loc[0]) {
        loc[0] = key;
#pragma unroll
        for (int i = 0; i < TOPK - 1; i++) {
            if (loc[i] > loc[i + 1]) {
                unsigned long long t = loc[i]; loc[i] = loc[i + 1]; loc[i + 1] = t;
            } else break;
        }
    }
}

__global__ void k_sel(const float* __restrict__ anchors, const float* __restrict__ ps,
                      const int* __restrict__ gtl)
{
    int row = (blockIdx.x * 256 + threadIdx.x) >> 5;   // global warp = row
    int lane = threadIdx.x & 31;
    int b = row >> 6;
    int n = row & 63;

    unsigned long long loc[TOPK];
#pragma unroll
    for (int i = 0; i < TOPK; i++) loc[i] = 0ull;

    int cnt = min(d_ccnt[row], CAP);
    const unsigned long long* buf = d_cand + (size_t)row * CAP;
    for (int i = lane; i < cnt; i += 32)
        topk_insert(loc, buf[i]);

    // recycle state for the next graph replay / pre-zero reduction targets
    if (lane == 0) {
        d_ccnt[row] = 0;
        d_maxam[row] = 0u;
        d_maxiou[row] = 0u;
    }

    bool my_spat = false;
    if (lane < 26) {
        const float* gp = d_gtg + row * GTS;
        float cx = __ldg(gp + 0), cy = __ldg(gp + 1);
        float cs = __ldg(gp + 2), sn = __ldg(gp + 3);
        float hw = __ldg(gp + 4), hh = __ldg(gp + 5);
        int id = lane;
        float px = __ldg(&anchors[2 * id]);
        float py = __ldg(&anchors[2 * id + 1]);
        float ma = 0.0f;
        my_spat = spatial_x(px, py, cx, cy, cs, sn, hw, hh);
        if (my_spat) {
            float ga = __ldg(gp + 6), gb = __ldg(gp + 7), gc = __ldg(gp + 8), gdet = __ldg(gp + 9);
            const float* pg = d_predg + ((size_t)b * LL + id) * 8;
            float iou = prob_iou_x(cx, cy, ga, gb, gc, gdet,
                                   pg[0], pg[1], pg[2], pg[3], pg[4], pg[5]);
            float cls = __ldg(ps + ((size_t)b * LL + id) * CC + __ldg(&gtl[row]));
            ma = align_x(cls, iou);
        }
        unsigned long long key =
            ((unsigned long long)__float_as_uint(ma) << 32) |
            (unsigned long long)(0xFFFFFFFFu - (unsigned)id);
        topk_insert(loc, key);
    }

    int consumed = 0;
    unsigned long long nbit = 1ull << n;
    for (int r = 0; r < TOPK; r++) {
        unsigned long long cand = (consumed < TOPK) ? loc[TOPK - 1 - consumed] : 0ull;
        unsigned long long mx = cand;
#pragma unroll
        for (int s = 16; s > 0; s >>= 1) {
            unsigned long long o = __shfl_xor_sync(0xFFFFFFFFu, mx, s);
            if (o > mx) mx = o;
        }
        if (cand == mx && mx != 0ull) {
            consumed++;
            bool sp_ok = ((mx >> 32) != 0ull) || my_spat;
            if (sp_ok) {
                unsigned l = 0xFFFFFFFFu - (unsigned)(mx & 0xFFFFFFFFull);
                atomicOr(&d_pos0[(size_t)b * LL + l], nbit);
            }
        }
    }
}

// ---------------- K2: assignment + dense zero-fill of scores region -------------
__global__ void k_assign(const float* __restrict__ ps, const float* __restrict__ gtb,
                         const int* __restrict__ gtl, const int* __restrict__ bgp,
                         float* __restrict__ out)
{
    int blk = blockIdx.x;
    int b = blk / NBLK_L;
    int l0 = (blk % NBLK_L) * 256;
    int tid = threadIdx.x;
    int l = l0 + tid;
    int lane = tid & 31;
    size_t gid = (size_t)b * LL + l;

    // dense zero-fill of this block's scores rows — fire-and-forget stores that
    // use the idle DRAM bandwidth while the latency chain below proceeds
    {
        float4 z4 = make_float4(0.f, 0.f, 0.f, 0.f);
        float4* sc4 = (float4*)(out + (size_t)BB * LL * 6 + ((size_t)b * LL + l0) * CC);
#pragma unroll
        for (int it = 0; it < 20; it++)
            sc4[tid + it * 256] = z4;
    }

    __shared__ unsigned int s_am[NN];
    __shared__ unsigned int s_iou[NN];
    if (tid < NN) { s_am[tid] = 0u; s_iou[tid] = 0u; }
    __syncthreads();

    const float* gtgb = d_gtg + b * NN * GTS;
    const int* labb = gtl + b * NN;
    const float* psr = ps + gid * CC;

    unsigned long long pos = d_pos0[gid] & __ldg(&d_padb[b]);

    // unconditional pred-param load (dead values for non-spat anchors; pos==0 there)
    const float* pg = d_predg + gid * 8;
    float4 p0 = ((const float4*)pg)[0];
    float4 p1 = ((const float4*)pg)[1];
    float px2 = p0.x, py2 = p0.y, pa = p0.z, pb_ = p0.w, pc = p1.x, pdet = p1.y;

    unsigned cmask = __ballot_sync(0xFFFFFFFFu, __popcll(pos) > 1);
    while (cmask) {
        int src = __ffs(cmask) - 1;
        cmask &= (cmask - 1);
        float bx2 = __shfl_sync(0xFFFFFFFFu, px2, src);
        float by2 = __shfl_sync(0xFFFFFFFFu, py2, src);
        float ba  = __shfl_sync(0xFFFFFFFFu, pa, src);
        float bb  = __shfl_sync(0xFFFFFFFFu, pb_, src);
        float bc  = __shfl_sync(0xFFFFFFFFu, pc, src);
        float bdt = __shfl_sync(0xFFFFFFFFu, pdet, src);
        const float* g0 = gtgb + lane * GTS;
        const float* g1 = gtgb + (lane + 32) * GTS;
        float i0 = prob_iou_x(__ldg(g0 + 0), __ldg(g0 + 1), __ldg(g0 + 6), __ldg(g0 + 7),
                              __ldg(g0 + 8), __ldg(g0 + 9), bx2, by2, ba, bb, bc, bdt);
        float i1 = prob_iou_x(__ldg(g1 + 0), __ldg(g1 + 1), __ldg(g1 + 6), __ldg(g1 + 7),
                              __ldg(g1 + 8), __ldg(g1 + 9), bx2, by2, ba, bb, bc, bdt);
        float mx = fmaxf(i0, i1);
#pragma unroll
        for (int s = 16; s > 0; s >>= 1)
            mx = fmaxf(mx, __shfl_xor_sync(0xFFFFFFFFu, mx, s));
        unsigned long long bits = 0ull;
        if (i0 == mx) bits |= (1ull << lane);
        if (i1 == mx) bits |= (1ull << (lane + 32));
#pragma unroll
        for (int s = 16; s > 0; s >>= 1)
            bits |= __shfl_xor_sync(0xFFFFFFFFu, bits, s);
        if (lane == src) pos = bits;
    }

    unsigned long long m = pos;
    while (m) {
        int n = __ffsll(m) - 1;
        m &= (m - 1);
        const float* g = gtgb + n * GTS;
        float iou = prob_iou_x(__ldg(g + 0), __ldg(g + 1), __ldg(g + 6), __ldg(g + 7),
                               __ldg(g + 8), __ldg(g + 9), px2, py2, pa, pb_, pc, pdet);
        float cls = __ldg(psr + __ldg(&labb[n]));
        float al = align_x(cls, iou);
        atomicMax(&s_am[n], __float_as_uint(al));
        atomicMax(&s_iou[n], __float_as_uint(iou));
    }

    bool fg = (pos != 0ull);
    int an = fg ? (__ffsll(pos) - 1) : 0;
    int bgv = *bgp;
    int lab = fg ? __ldg(&labb[an]) : bgv;

    out[gid] = (float)lab;                                 // assigned_labels
    const float* gbx = gtb + ((size_t)b * NN + an) * 5;
    float* ob = out + (size_t)BB * LL + gid * 5;           // assigned_bboxes
#pragma unroll
    for (int i = 0; i < 5; i++) ob[i] = fg ? gbx[i] : 0.0f;

    d_poslab[gid] = make_ulonglong2(pos, (unsigned long long)lab);

    __syncthreads();
    if (tid < NN) {
        unsigned int v = s_am[tid];
        if (v) atomicMax(&d_maxam[b * NN + tid], v);
    } else if (tid < 2 * NN) {
        unsigned int v = s_iou[tid - NN];
        if (v) atomicMax(&d_maxiou[b * NN + tid - NN], v);
    }
}

// ---------------- K3: SPARSE norm write (scores pre-zeroed in k_assign) ---------
__global__ void k_scores(const float* __restrict__ ps, const int* __restrict__ gtl,
                         float* __restrict__ out)
{
    int blk = blockIdx.x;
    int b = blk / NBLK_L;
    int l = (blk % NBLK_L) * 256 + threadIdx.x;
    size_t gid = (size_t)b * LL + l;

    ulonglong2 pl = d_poslab[gid];
    unsigned long long pos = pl.x;
    if (!pos) return;

    const float* pg = d_predg + gid * 8;
    float4 p0 = ((const float4*)pg)[0];
    float4 p1 = ((const float4*)pg)[1];
    const float* psr = ps + gid * CC;
    float norm = 0.0f;
    unsigned long long m = pos;
    while (m) {
        int n = __ffsll(m) - 1;
        m &= (m - 1);
        int row = b * NN + n;
        const float* g = d_gtg + row * GTS;
        float iou = prob_iou_x(g[0], g[1], g[6], g[7], g[8], g[9],
                               p0.x, p0.y, p0.z, p0.w, p1.x, p1.y);
        float cls = __ldg(psr + gtl[row]);
        float al = align_x(cls, iou);
        float ma = __uint_as_float(d_maxam[row]);
        float mi = __uint_as_float(d_maxiou[row]);
        float v = __fmul_rn(__fdiv_rn(al, __fadd_rn(ma, 1e-9f)), mi);
        norm = fmaxf(norm, v);
    }
    int lab = (int)pl.y;
    out[(size_t)BB * LL * 6 + gid * CC + lab] = norm;
}

// ---------------- launch ----------------
extern "C" void kernel_launch(void* const* d_in, const int* in_sizes, int n_in,
                              void* d_out, int out_size)
{
    const float* pred_scores = (const float*)d_in[0];   // (B,L,C)
    const float* pred_bboxes = (const float*)d_in[1];   // (B,L,5)
    const float* anchors     = (const float*)d_in[2];   // (1,L,2)
    const int*   gt_labels   = (const int*)d_in[3];     // (B,N,1)
    const float* gt_bboxes   = (const float*)d_in[4];   // (B,N,5)
    const float* pad_mask    = (const float*)d_in[5];   // (B,N,1)
    const int*   bg_index    = (const int*)d_in[6];     // scalar
    float* out = (float*)d_out;

    k_cand<<<BB * NBLK_L, 256>>>(anchors, pred_scores, pred_bboxes,
                                 gt_bboxes, gt_labels, pad_mask);
    k_sel<<<(BB * NN) / 8, 256>>>(anchors, pred_scores, gt_labels);
    k_assign<<<BB * NBLK_L, 256>>>(pred_scores, gt_bboxes, gt_labels, bg_index, out);
    k_scores<<<BB * NBLK_L, 256>>>(pred_scores, gt_labels, out);
}

// round 17
// speedup vs baseline: 1.2167x; 1.0568x over previous
#include <cuda_runtime.h>
#include <math.h>

#define BB 16
#define LL 21504
#define NN 64
#define CC 80
#define GTS 12           // gt param stride
#define TOPK 13
#define NBLK_L 84        // 21504 / 256
#define CAP 1024         // per-(b,n) candidate buffer

// ---------------- scratch (__device__ globals; no allocation) ----------------
__device__ float d_predg[(size_t)BB * LL * 8];          // x,y,a,b,c,det (spat anchors only)
__device__ float d_gtg[BB * NN * GTS];                  // cx,cy,cos,sin,hw,hh,a,b,c,det,pad
__device__ unsigned long long d_padb[BB];               // pad bitmask per batch
__device__ unsigned int d_maxam[BB * NN];               // float bits, atomicMax (nonneg)
__device__ unsigned int d_maxiou[BB * NN];
__device__ unsigned long long d_pos0[(size_t)BB * LL];  // topk&spatial membership bitmask
__device__ ulonglong2 d_poslab[(size_t)BB * LL];        // {final pos bitmask, label}
__device__ int d_fgcnt;                                 // compact fg list (zeroed in k_sel)
__device__ int d_fglist[(size_t)BB * LL];
// candidate buffers (d_ccnt recycled: zeroed by k_sel each call -> replay-safe)
__device__ int d_ccnt[BB * NN];
__device__ unsigned long long d_cand[(size_t)BB * NN * CAP];

// ---------------- bit-exact XLA-shadow ProbIoU ----------------
__device__ __forceinline__ float prob_iou_x(
    float x1, float y1, float a1, float b1, float c1, float det1,
    float x2, float y2, float a2, float b2, float c2, float det2)
{
    float A  = __fadd_rn(a1, a2);
    float Bv = __fadd_rn(b1, b2);
    float Cv = __fadd_rn(c1, c2);
    float denom = __fadd_rn(__fsub_rn(__fmul_rn(A, Bv), __fmul_rn(Cv, Cv)), 1e-7f);
    float dy = __fsub_rn(y1, y2);
    float dx = __fsub_rn(x1, x2);
    float xd = __fsub_rn(x2, x1);
    float t1 = __fdiv_rn(
        __fmul_rn(0.25f, __fadd_rn(__fmul_rn(A, __fmul_rn(dy, dy)),
                                   __fmul_rn(Bv, __fmul_rn(dx, dx)))),
        denom);
    float t2 = __fdiv_rn(
        __fmul_rn(0.5f, __fmul_rn(__fmul_rn(Cv, xd), dy)),
        denom);
    float sq   = __fsqrt_rn(__fmul_rn(det1, det2));
    float den2 = __fadd_rn(__fmul_rn(4.0f, sq), 1e-7f);
    float arg  = __fadd_rn(__fdiv_rn(denom, den2), 1e-7f);
    float t3   = __fmul_rn(0.5f, logf(arg));
    float bd = fminf(fmaxf(__fadd_rn(__fadd_rn(t1, t2), t3), 1e-7f), 100.0f);
    float e  = expf(-bd);
    float s  = __fadd_rn(__fsub_rn(1.0f, e), 1e-7f);
    float hd = __fsqrt_rn(s);
    return fminf(fmaxf(__fsub_rn(1.0f, hd), 0.0f), 1.0f);
}

// align = cls * iou^6 under XLA GPU FTZ semantics (confirmed R4/R6)
__device__ __forceinline__ float align_x(float cls, float iou)
{
    float i2 = __fmul_rn(iou, iou);
    float p6 = __fmul_rn(__fmul_rn(i2, i2), i2);
    if (iou < 0x1p-21f) p6 = 0.0f;
    float al = __fmul_rn(cls, p6);
    if (al < 0x1p-126f) al = 0.0f;
    return al;
}

__device__ __forceinline__ bool spatial_x(float px, float py,
                                          float cx, float cy, float cs, float sn,
                                          float hw, float hh)
{
    float dx = __fsub_rn(px, cx);
    float dy = __fsub_rn(py, cy);
    float sna = -sn;
    float lx = __fsub_rn(__fmul_rn(dx, cs), __fmul_rn(dy, sna));
    float ly = __fadd_rn(__fmul_rn(dx, sna), __fmul_rn(dy, cs));
    return (fabsf(lx) <= hw) && (fabsf(ly) <= hh);
}

__device__ __forceinline__ void gbb_x(float w, float h, float cs, float sn,
                                      float& a, float& b, float& c, float& det)
{
    const float r12 = 1.0f / 12.0f;
    float w2 = __fmul_rn(__fmul_rn(w, w), r12);
    float h2 = __fmul_rn(__fmul_rn(h, h), r12);
    a = __fadd_rn(__fmul_rn(__fmul_rn(w2, cs), cs), __fmul_rn(__fmul_rn(h2, sn), sn));
    b = __fadd_rn(__fmul_rn(__fmul_rn(w2, sn), sn), __fmul_rn(__fmul_rn(h2, cs), cs));
    c = __fmul_rn(__fmul_rn(__fsub_rn(w2, h2), cs), sn);
    det = fmaxf(__fsub_rn(__fmul_rn(a, b), __fmul_rn(c, c)), 0.0f);
}

// ---------------- K_cand: GT params in smem, lazy pred params, spatial mask,
//                  candidate push + FIRST HALF of the scores zero-fill ----------
__global__ void k_cand(const float* __restrict__ anchors, const float* __restrict__ ps,
                       const float* __restrict__ pb, const float* __restrict__ gtb,
                       const int* __restrict__ gtl, const float* __restrict__ pad,
                       float* __restrict__ out)
{
    int blk = blockIdx.x;
    int b = blk / NBLK_L;
    int l0 = (blk % NBLK_L) * 256;
    int tid = threadIdx.x;
    int l = l0 + tid;
    size_t gid = (size_t)b * LL + l;

    // zero-fill first half of this block's scores rows (fire-and-forget; overlaps
    // the smem setup + spatial latency chain below)
    {
        float4 z4 = make_float4(0.f, 0.f, 0.f, 0.f);
        float4* sc4 = (float4*)(out + (size_t)BB * LL * 6 + ((size_t)b * LL + l0) * CC);
#pragma unroll
        for (int it = 0; it < 10; it++)
            sc4[tid + it * 256] = z4;
    }

    __shared__ float4 sgA[NN];      // cx, cy, cs, sn
    __shared__ float2 sgB[NN];      // hw, hh
    __shared__ float sg[NN * GTS];  // full params (iou path)
    __shared__ int sL[NN];
    __shared__ unsigned s_padw[2];

    if (tid < NN) {
        const float* p = gtb + (size_t)(b * NN + tid) * 5;
        float cx = p[0], cy = p[1], w = p[2], h = p[3], ang = p[4];
        float cs = cosf(ang), sn = sinf(ang);
        float a, bb_, c, det;
        gbb_x(w, h, cs, sn, a, bb_, c, det);
        float* o = sg + tid * GTS;
        o[0] = cx; o[1] = cy; o[2] = cs; o[3] = sn;
        o[4] = __fmul_rn(w, 0.5f); o[5] = __fmul_rn(h, 0.5f);
        o[6] = a; o[7] = bb_; o[8] = c; o[9] = det;
        o[10] = 0.0f; o[11] = 0.0f;
        sgA[tid] = make_float4(cx, cy, cs, sn);
        sgB[tid] = make_float2(o[4], o[5]);
        sL[tid] = gtl[b * NN + tid];
        bool pd = pad[b * NN + tid] > 0.0f;
        unsigned bal = __ballot_sync(0xFFFFFFFFu, pd);
        if ((tid & 31) == 0) s_padw[tid >> 5] = bal;
    }
    d_pos0[gid] = 0ull;
    __syncthreads();

    // per-batch leader block publishes GT params + pad bitmask for later kernels
    if ((blk % NBLK_L) == 0) {
        for (int i = tid; i < NN * GTS; i += 256) d_gtg[b * NN * GTS + i] = sg[i];
        if (tid == 0)
            d_padb[b] = ((unsigned long long)s_padw[1] << 32) | (unsigned long long)s_padw[0];
    }

    float px = anchors[2 * l], py = anchors[2 * l + 1];

    unsigned long long spat = 0ull;
#pragma unroll 8
    for (int n = 0; n < NN; n++) {
        float4 A = sgA[n];
        float2 Bv = sgB[n];
        if (spatial_x(px, py, A.x, A.y, A.z, A.w, Bv.x, Bv.y))
            spat |= (1ull << n);
    }

    if (spat) {
        // lazy pred gaussian params (only ~30% of anchors reach here)
        const float* p = pb + gid * 5;
        float cx = p[0], cy = p[1], w = p[2], h = p[3], ang = p[4];
        float cs = cosf(ang), sn = sinf(ang);
        float a, bb_, c, det;
        gbb_x(w, h, cs, sn, a, bb_, c, det);
        float4 p0 = make_float4(cx, cy, a, bb_);
        float4 p1 = make_float4(c, det, 0.0f, 0.0f);
        float* o = d_predg + gid * 8;
        ((float4*)o)[0] = p0;
        ((float4*)o)[1] = p1;

        if (l >= 26) {
            const float* psr = ps + gid * CC;
            unsigned long long m = spat;
            unsigned long long key_lo = (unsigned long long)(0xFFFFFFFFu - (unsigned)l);
            while (m) {
                int n = __ffsll(m) - 1;
                m &= (m - 1);
                const float* g = sg + n * GTS;
                float iou = prob_iou_x(g[0], g[1], g[6], g[7], g[8], g[9],
                                       p0.x, p0.y, p0.z, p0.w, p1.x, p1.y);
                float cls = __ldg(psr + sL[n]);
                float al = align_x(cls, iou);
                if (al > 0.0f) {
                    int row = b * NN + n;
                    int slot = atomicAdd(&d_ccnt[row], 1);
                    if (slot < CAP)
                        d_cand[(size_t)row * CAP + slot] =
                            ((unsigned long long)__float_as_uint(al) << 32) | key_lo;
                }
            }
        }
    }
}

// ---------------- K_sel: exact top-13 per row; recycles counters for replay -----
__device__ __forceinline__ void topk_insert(unsigned long long* loc, unsigned long long key)
{
    if (key > loc[0]) {
        loc[0] = key;
#pragma unroll
        for (int i = 0; i < TOPK - 1; i++) {
            if (loc[i] > loc[i + 1]) {
                unsigned long long t = loc[i]; loc[i] = loc[i + 1]; loc[i + 1] = t;
            } else break;
        }
    }
}

__global__ void k_sel(const float* __restrict__ anchors, const float* __restrict__ ps,
                      const int* __restrict__ gtl)
{
    int row = (blockIdx.x * 256 + threadIdx.x) >> 5;   // global warp = row
    int lane = threadIdx.x & 31;
    int b = row >> 6;
    int n = row & 63;

    unsigned long long loc[TOPK];
#pragma unroll
    for (int i = 0; i < TOPK; i++) loc[i] = 0ull;

    int cnt = min(d_ccnt[row], CAP);
    const unsigned long long* buf = d_cand + (size_t)row * CAP;
    for (int i = lane; i < cnt; i += 32)
        topk_insert(loc, buf[i]);

    // recycle state for the next graph replay / pre-zero reduction targets
    if (lane == 0) {
        d_ccnt[row] = 0;
        d_maxam[row] = 0u;
        d_maxiou[row] = 0u;
        if (row == 0) d_fgcnt = 0;
    }

    bool my_spat = false;
    if (lane < 26) {
        const float* gp = d_gtg + row * GTS;
        float cx = __ldg(gp + 0), cy = __ldg(gp + 1);
        float cs = __ldg(gp + 2), sn = __ldg(gp + 3);
        float hw = __ldg(gp + 4), hh = __ldg(gp + 5);
        int id = lane;
        float px = __ldg(&anchors[2 * id]);
        float py = __ldg(&anchors[2 * id + 1]);
        float ma = 0.0f;
        my_spat = spatial_x(px, py, cx, cy, cs, sn, hw, hh);
        if (my_spat) {
            float ga = __ldg(gp + 6), gb = __ldg(gp + 7), gc = __ldg(gp + 8), gdet = __ldg(gp + 9);
            const float* pg = d_predg + ((size_t)b * LL + id) * 8;
            float iou = prob_iou_x(cx, cy, ga, gb, gc, gdet,
                                   pg[0], pg[1], pg[2], pg[3], pg[4], pg[5]);
            float cls = __ldg(ps + ((size_t)b * LL + id) * CC + __ldg(&gtl[row]));
            ma = align_x(cls, iou);
        }
        unsigned long long key =
            ((unsigned long long)__float_as_uint(ma) << 32) |
            (unsigned long long)(0xFFFFFFFFu - (unsigned)id);
        topk_insert(loc, key);
    }

    int consumed = 0;
    unsigned long long nbit = 1ull << n;
    for (int r = 0; r < TOPK; r++) {
        unsigned long long cand = (consumed < TOPK) ? loc[TOPK - 1 - consumed] : 0ull;
        unsigned long long mx = cand;
#pragma unroll
        for (int s = 16; s > 0; s >>= 1) {
            unsigned long long o = __shfl_xor_sync(0xFFFFFFFFu, mx, s);
            if (o > mx) mx = o;
        }
        if (cand == mx && mx != 0ull) {
            consumed++;
            bool sp_ok = ((mx >> 32) != 0ull) || my_spat;
            if (sp_ok) {
                unsigned l = 0xFFFFFFFFu - (unsigned)(mx & 0xFFFFFFFFull);
                atomicOr(&d_pos0[(size_t)b * LL + l], nbit);
            }
        }
    }
}

// ---------------- K2: assignment + second half of zero-fill + fg compaction -----
__global__ void k_assign(const float* __restrict__ ps, const float* __restrict__ gtb,
                         const int* __restrict__ gtl, const int* __restrict__ bgp,
                         float* __restrict__ out)
{
    int blk = blockIdx.x;
    int b = blk / NBLK_L;
    int l0 = (blk % NBLK_L) * 256;
    int tid = threadIdx.x;
    int l = l0 + tid;
    int lane = tid & 31;
    size_t gid = (size_t)b * LL + l;

    // zero-fill second half of this block's scores rows
    {
        float4 z4 = make_float4(0.f, 0.f, 0.f, 0.f);
        float4* sc4 = (float4*)(out + (size_t)BB * LL * 6 + ((size_t)b * LL + l0) * CC);
#pragma unroll
        for (int it = 10; it < 20; it++)
            sc4[tid + it * 256] = z4;
    }

    __shared__ unsigned int s_am[NN];
    __shared__ unsigned int s_iou[NN];
    if (tid < NN) { s_am[tid] = 0u; s_iou[tid] = 0u; }
    __syncthreads();

    const float* gtgb = d_gtg + b * NN * GTS;
    const int* labb = gtl + b * NN;
    const float* psr = ps + gid * CC;

    unsigned long long pos = d_pos0[gid] & __ldg(&d_padb[b]);

    // unconditional pred-param load (dead values for non-spat anchors; pos==0 there)
    const float* pg = d_predg + gid * 8;
    float4 p0 = ((const float4*)pg)[0];
    float4 p1 = ((const float4*)pg)[1];
    float px2 = p0.x, py2 = p0.y, pa = p0.z, pb_ = p0.w, pc = p1.x, pdet = p1.y;

    unsigned cmask = __ballot_sync(0xFFFFFFFFu, __popcll(pos) > 1);
    while (cmask) {
        int src = __ffs(cmask) - 1;
        cmask &= (cmask - 1);
        float bx2 = __shfl_sync(0xFFFFFFFFu, px2, src);
        float by2 = __shfl_sync(0xFFFFFFFFu, py2, src);
        float ba  = __shfl_sync(0xFFFFFFFFu, pa, src);
        float bb  = __shfl_sync(0xFFFFFFFFu, pb_, src);
        float bc  = __shfl_sync(0xFFFFFFFFu, pc, src);
        float bdt = __shfl_sync(0xFFFFFFFFu, pdet, src);
        const float* g0 = gtgb + lane * GTS;
        const float* g1 = gtgb + (lane + 32) * GTS;
        float i0 = prob_iou_x(__ldg(g0 + 0), __ldg(g0 + 1), __ldg(g0 + 6), __ldg(g0 + 7),
                              __ldg(g0 + 8), __ldg(g0 + 9), bx2, by2, ba, bb, bc, bdt);
        float i1 = prob_iou_x(__ldg(g1 + 0), __ldg(g1 + 1), __ldg(g1 + 6), __ldg(g1 + 7),
                              __ldg(g1 + 8), __ldg(g1 + 9), bx2, by2, ba, bb, bc, bdt);
        float mx = fmaxf(i0, i1);
#pragma unroll
        for (int s = 16; s > 0; s >>= 1)
            mx = fmaxf(mx, __shfl_xor_sync(0xFFFFFFFFu, mx, s));
        unsigned long long bits = 0ull;
        if (i0 == mx) bits |= (1ull << lane);
        if (i1 == mx) bits |= (1ull << (lane + 32));
#pragma unroll
        for (int s = 16; s > 0; s >>= 1)
            bits |= __shfl_xor_sync(0xFFFFFFFFu, bits, s);
        if (lane == src) pos = bits;
    }

    unsigned long long m = pos;
    while (m) {
        int n = __ffsll(m) - 1;
        m &= (m - 1);
        const float* g = gtgb + n * GTS;
        float iou = prob_iou_x(__ldg(g + 0), __ldg(g + 1), __ldg(g + 6), __ldg(g + 7),
                               __ldg(g + 8), __ldg(g + 9), px2, py2, pa, pb_, pc, pdet);
        float cls = __ldg(psr + __ldg(&labb[n]));
        float al = align_x(cls, iou);
        atomicMax(&s_am[n], __float_as_uint(al));
        atomicMax(&s_iou[n], __float_as_uint(iou));
    }

    bool fg = (pos != 0ull);
    int an = fg ? (__ffsll(pos) - 1) : 0;
    int bgv = *bgp;
    int lab = fg ? __ldg(&labb[an]) : bgv;

    out[gid] = (float)lab;                                 // assigned_labels
    const float* gbx = gtb + ((size_t)b * NN + an) * 5;
    float* ob = out + (size_t)BB * LL + gid * 5;           // assigned_bboxes
#pragma unroll
    for (int i = 0; i < 5; i++) ob[i] = fg ? gbx[i] : 0.0f;

    if (fg) d_poslab[gid] = make_ulonglong2(pos, (unsigned long long)lab);

    // warp-aggregated fg compaction
    {
        unsigned fmask = __ballot_sync(0xFFFFFFFFu, fg);
        int nfg = __popc(fmask);
        int base = 0;
        if (lane == 0 && nfg) base = atomicAdd(&d_fgcnt, nfg);
        base = __shfl_sync(0xFFFFFFFFu, base, 0);
        if (fg) {
            int off = __popc(fmask & ((1u << lane) - 1u));
            d_fglist[base + off] = (int)gid;
        }
    }

    __syncthreads();
    if (tid < NN) {
        unsigned int v = s_am[tid];
        if (v) atomicMax(&d_maxam[b * NN + tid], v);
    } else if (tid < 2 * NN) {
        unsigned int v = s_iou[tid - NN];
        if (v) atomicMax(&d_maxiou[b * NN + tid - NN], v);
    }
}

// ---------------- K3: SPARSE norm write over compact fg list --------------------
__global__ void k_scores(const float* __restrict__ ps, const int* __restrict__ gtl,
                         float* __restrict__ out)
{
    int i = blockIdx.x * 256 + threadIdx.x;
    if (i >= d_fgcnt) return;
    size_t gid = (size_t)d_fglist[i];
    int b = (int)(gid / LL);

    ulonglong2 pl = d_poslab[gid];
    unsigned long long pos = pl.x;

    const float* pg = d_predg + gid * 8;
    float4 p0 = ((const float4*)pg)[0];
    float4 p1 = ((const float4*)pg)[1];
    const float* psr = ps + gid * CC;
    float norm = 0.0f;
    unsigned long long m = pos;
    while (m) {
        int n = __ffsll(m) - 1;
        m &= (m - 1);
        int row = b * NN + n;
        const float* g = d_gtg + row * GTS;
        float iou = prob_iou_x(g[0], g[1], g[6], g[7], g[8], g[9],
                               p0.x, p0.y, p0.z, p0.w, p1.x, p1.y);
        float cls = __ldg(psr + gtl[row]);
        float al = align_x(cls, iou);
        float ma = __uint_as_float(d_maxam[row]);
        float mi = __uint_as_float(d_maxiou[row]);
        float v = __fmul_rn(__fdiv_rn(al, __fadd_rn(ma, 1e-9f)), mi);
        norm = fmaxf(norm, v);
    }
    int lab = (int)pl.y;
    out[(size_t)BB * LL * 6 + gid * CC + lab] = norm;
}

// ---------------- launch ----------------
extern "C" void kernel_launch(void* const* d_in, const int* in_sizes, int n_in,
                              void* d_out, int out_size)
{
    const float* pred_scores = (const float*)d_in[0];   // (B,L,C)
    const float* pred_bboxes = (const float*)d_in[1];   // (B,L,5)
    const float* anchors     = (const float*)d_in[2];   // (1,L,2)
    const int*   gt_labels   = (const int*)d_in[3];     // (B,N,1)
    const float* gt_bboxes   = (const float*)d_in[4];   // (B,N,5)
    const float* pad_mask    = (const float*)d_in[5];   // (B,N,1)
    const int*   bg_index    = (const int*)d_in[6];     // scalar
    float* out = (float*)d_out;

    k_cand<<<BB * NBLK_L, 256>>>(anchors, pred_scores, pred_bboxes,
                                 gt_bboxes, gt_labels, pad_mask, out);
    k_sel<<<(BB * NN) / 8, 256>>>(anchors, pred_scores, gt_labels);
    k_assign<<<BB * NBLK_L, 256>>>(pred_scores, gt_bboxes, gt_labels, bg_index, out);
    k_scores<<<BB * NBLK_L, 256>>>(pred_scores, gt_labels, out);
}